// round 1
// baseline (speedup 1.0000x reference)
#include <cuda_runtime.h>
#include <cuda_bf16.h>
#include <math.h>

// Problem constants
#define BATCH   64
#define NTOK    197
#define CH      768
#define NHEAD   12
#define HDIM    64
#define MROWS   (BATCH * NTOK)      // 12608
#define QKV_N   (3 * CH)            // 2304

// Scratch buffers (allocation-free rule: __device__ globals)
__device__ float g_h[(size_t)MROWS * QKV_N];    // QKV output: [12608, 2304]
__device__ float g_att[(size_t)MROWS * CH];     // attention output: [12608, 768]

// ---------------------------------------------------------------------------
// Tiled SGEMM:  C[M,N] = A[M,K] @ B[N,K]^T + bias[N]
// BM=BN=128, BK=16, 256 threads, 8x8 per thread, float4 global loads.
// N and K are multiples of 128/16; only M needs guarding.
// ---------------------------------------------------------------------------
__global__ __launch_bounds__(256, 2)
void sgemm_nt_bias(const float* __restrict__ A,
                   const float* __restrict__ B,
                   const float* __restrict__ bias,
                   float* __restrict__ C,
                   int M, int N, int K)
{
    __shared__ float As[16][128];
    __shared__ float Bs[16][128];

    const int tid = threadIdx.x;
    const int bm = blockIdx.y * 128;
    const int bn = blockIdx.x * 128;

    const int trow = (tid / 16) * 8;   // 0..120
    const int tcol = (tid % 16) * 8;   // 0..120

    const int lr = tid >> 2;           // 0..63
    const int lc = (tid & 3) * 4;      // 0,4,8,12

    float acc[8][8];
#pragma unroll
    for (int i = 0; i < 8; i++)
#pragma unroll
        for (int j = 0; j < 8; j++) acc[i][j] = 0.0f;

    for (int k0 = 0; k0 < K; k0 += 16) {
#pragma unroll
        for (int h = 0; h < 2; h++) {
            int r = lr + h * 64;
            int gm = bm + r;
            float4 va;
            if (gm < M) {
                va = *(const float4*)(A + (size_t)gm * K + k0 + lc);
            } else {
                va = make_float4(0.f, 0.f, 0.f, 0.f);
            }
            As[lc + 0][r] = va.x;
            As[lc + 1][r] = va.y;
            As[lc + 2][r] = va.z;
            As[lc + 3][r] = va.w;

            float4 vb = *(const float4*)(B + (size_t)(bn + r) * K + k0 + lc);
            Bs[lc + 0][r] = vb.x;
            Bs[lc + 1][r] = vb.y;
            Bs[lc + 2][r] = vb.z;
            Bs[lc + 3][r] = vb.w;
        }
        __syncthreads();

#pragma unroll
        for (int kk = 0; kk < 16; kk++) {
            float ra[8], rb[8];
            // vectorized smem reads
            float4 a0 = *(const float4*)&As[kk][trow];
            float4 a1 = *(const float4*)&As[kk][trow + 4];
            float4 b0 = *(const float4*)&Bs[kk][tcol];
            float4 b1 = *(const float4*)&Bs[kk][tcol + 4];
            ra[0] = a0.x; ra[1] = a0.y; ra[2] = a0.z; ra[3] = a0.w;
            ra[4] = a1.x; ra[5] = a1.y; ra[6] = a1.z; ra[7] = a1.w;
            rb[0] = b0.x; rb[1] = b0.y; rb[2] = b0.z; rb[3] = b0.w;
            rb[4] = b1.x; rb[5] = b1.y; rb[6] = b1.z; rb[7] = b1.w;
#pragma unroll
            for (int i = 0; i < 8; i++)
#pragma unroll
                for (int j = 0; j < 8; j++)
                    acc[i][j] = fmaf(ra[i], rb[j], acc[i][j]);
        }
        __syncthreads();
    }

    // Epilogue: add bias, store (guard M)
#pragma unroll
    for (int i = 0; i < 8; i++) {
        int gm = bm + trow + i;
        if (gm >= M) continue;
        float* cptr = C + (size_t)gm * N + bn + tcol;
        const float* bptr = bias + bn + tcol;
#pragma unroll
        for (int j4 = 0; j4 < 2; j4++) {
            float4 v;
            v.x = acc[i][j4 * 4 + 0] + bptr[j4 * 4 + 0];
            v.y = acc[i][j4 * 4 + 1] + bptr[j4 * 4 + 1];
            v.z = acc[i][j4 * 4 + 2] + bptr[j4 * 4 + 2];
            v.w = acc[i][j4 * 4 + 3] + bptr[j4 * 4 + 3];
            *(float4*)(cptr + j4 * 4) = v;
        }
    }
}

// ---------------------------------------------------------------------------
// Fused attention: one CTA per (batch, head). 256 threads (8 warps).
// K stored transposed in smem (Kt[64][200], conflict-free in the score loop),
// V stored row-major (Vs[197][64], conflict-free in the AV loop).
// Each warp owns rows row = warp, warp+8, ... Online per-row softmax.
// smem: Kt 12800 + V 12608 + q 512 + p 1600 = 27520 floats = 110080 B
// ---------------------------------------------------------------------------
#define KT_LD   200
#define SMEM_FLOATS (64 * KT_LD + NTOK * HDIM + 8 * HDIM + 8 * KT_LD)

__global__ __launch_bounds__(256, 1)
void attn_kernel(const float* __restrict__ h, float* __restrict__ out)
{
    extern __shared__ float smem[];
    float* Kt = smem;                          // [64][200]
    float* Vs = Kt + 64 * KT_LD;               // [197][64]
    float* Qb = Vs + NTOK * HDIM;              // [8][64]
    float* Pb = Qb + 8 * HDIM;                 // [8][200]

    const int bh = blockIdx.x;
    const int b  = bh / NHEAD;
    const int hd = bh % NHEAD;

    const int tid  = threadIdx.x;
    const int w    = tid >> 5;
    const int lane = tid & 31;

    const float* hb = h + (size_t)b * NTOK * QKV_N;
    const int kcol = CH + hd * HDIM;           // K offset within row
    const int vcol = 2 * CH + hd * HDIM;       // V offset within row
    const int qcol = hd * HDIM;

    // Load K (transposed) and V into smem, coalesced on the d axis.
    for (int idx = tid; idx < NTOK * HDIM; idx += 256) {
        int j = idx >> 6;
        int d = idx & 63;
        float kv = hb[(size_t)j * QKV_N + kcol + d];
        float vv = hb[(size_t)j * QKV_N + vcol + d];
        Kt[d * KT_LD + j] = kv;
        Vs[j * HDIM + d]  = vv;
    }
    __syncthreads();

    const float scale = 0.125f;   // 1/sqrt(64)

    for (int row = w; row < NTOK; row += 8) {
        // stage q row in smem (broadcast-friendly)
        for (int d = lane; d < HDIM; d += 32)
            Qb[w * HDIM + d] = hb[(size_t)row * QKV_N + qcol + d];
        __syncwarp();

        float s[7];
#pragma unroll
        for (int jj = 0; jj < 7; jj++) s[jj] = 0.0f;

#pragma unroll 4
        for (int d = 0; d < HDIM; d++) {
            float qd = Qb[w * HDIM + d];
            const float* krow = Kt + d * KT_LD;
#pragma unroll
            for (int jj = 0; jj < 7; jj++)
                s[jj] = fmaf(qd, krow[lane + jj * 32], s[jj]);
        }

        // mask + scale
        float mx = -INFINITY;
#pragma unroll
        for (int jj = 0; jj < 7; jj++) {
            int j = lane + jj * 32;
            if (j < NTOK) { s[jj] *= scale; mx = fmaxf(mx, s[jj]); }
            else s[jj] = -INFINITY;
        }
        // warp max
#pragma unroll
        for (int o = 16; o > 0; o >>= 1)
            mx = fmaxf(mx, __shfl_xor_sync(0xffffffffu, mx, o));

        float sum = 0.0f;
#pragma unroll
        for (int jj = 0; jj < 7; jj++) {
            s[jj] = expf(s[jj] - mx);   // expf(-inf)=0 handles mask
            sum += s[jj];
        }
#pragma unroll
        for (int o = 16; o > 0; o >>= 1)
            sum += __shfl_xor_sync(0xffffffffu, sum, o);
        float inv = 1.0f / sum;

        // write normalized probs to smem
#pragma unroll
        for (int jj = 0; jj < 7; jj++) {
            int j = lane + jj * 32;
            if (j < NTOK) Pb[w * KT_LD + j] = s[jj] * inv;
        }
        __syncwarp();

        // AV: each lane owns 2 output dims
        float* orow = out + ((size_t)b * NTOK + row) * CH + hd * HDIM;
        const float* prow = Pb + w * KT_LD;
#pragma unroll
        for (int dd = 0; dd < 2; dd++) {
            int d = lane + dd * 32;
            float acc = 0.0f;
#pragma unroll 4
            for (int j = 0; j < NTOK; j++)
                acc = fmaf(prow[j], Vs[j * HDIM + d], acc);
            orow[d] = acc;
        }
        __syncwarp();
    }
}

// ---------------------------------------------------------------------------
// Launch
// ---------------------------------------------------------------------------
extern "C" void kernel_launch(void* const* d_in, const int* in_sizes, int n_in,
                              void* d_out, int out_size)
{
    const float* x      = (const float*)d_in[0];
    const float* qkv_w  = (const float*)d_in[1];
    const float* qkv_b  = (const float*)d_in[2];
    const float* proj_w = (const float*)d_in[3];
    const float* proj_b = (const float*)d_in[4];
    float* out = (float*)d_out;

    float* h_buf;
    float* att_buf;
    cudaGetSymbolAddress((void**)&h_buf, g_h);
    cudaGetSymbolAddress((void**)&att_buf, g_att);

    // 1) QKV GEMM: [12608, 2304] = x[12608,768] @ W[2304,768]^T + b
    {
        dim3 grid(QKV_N / 128, (MROWS + 127) / 128);   // 18 x 99
        sgemm_nt_bias<<<grid, 256>>>(x, qkv_w, qkv_b, h_buf, MROWS, QKV_N, CH);
    }

    // 2) fused attention, one CTA per (b, head)
    {
        size_t smem_bytes = (size_t)SMEM_FLOATS * sizeof(float);   // 110080
        cudaFuncSetAttribute(attn_kernel,
                             cudaFuncAttributeMaxDynamicSharedMemorySize,
                             (int)smem_bytes);
        attn_kernel<<<BATCH * NHEAD, 256, smem_bytes>>>(h_buf, att_buf);
    }

    // 3) proj GEMM: out[12608,768] = att[12608,768] @ Wp[768,768]^T + bp
    {
        dim3 grid(CH / 128, (MROWS + 127) / 128);      // 6 x 99
        sgemm_nt_bias<<<grid, 256>>>(att_buf, proj_w, proj_b, out, MROWS, CH, CH);
    }
}

// round 9
// speedup vs baseline: 1.6811x; 1.6811x over previous
#include <cuda_runtime.h>
#include <cuda_bf16.h>
#include <math.h>
#include <cstdint>

// Problem constants
#define BATCH   64
#define NTOK    197
#define CH      768
#define NHEAD   12
#define HDIM    64
#define MROWS   (BATCH * NTOK)      // 12608
#define MPAD    12672               // 99 * 128
#define QKV_N   (3 * CH)            // 2304
#define KDIM    768
#define KCHUNK  64                  // bf16 elems per K chunk (= 128 bytes/row)

// ---------------------------------------------------------------------------
// Scratch (__device__ globals; no allocation allowed). 256B-aligned for 16B
// vector/cp.async loads.
// ---------------------------------------------------------------------------
__device__ __align__(256) float         g_h[(size_t)MPAD * QKV_N];   // QKV out fp32
__device__ __align__(256) __nv_bfloat16 g_xhi[(size_t)MPAD * CH];
__device__ __align__(256) __nv_bfloat16 g_xlo[(size_t)MPAD * CH];
__device__ __align__(256) __nv_bfloat16 g_whi[(size_t)QKV_N * CH];
__device__ __align__(256) __nv_bfloat16 g_wlo[(size_t)QKV_N * CH];
__device__ __align__(256) __nv_bfloat16 g_ahi[(size_t)MPAD * CH];   // attn out hi
__device__ __align__(256) __nv_bfloat16 g_alo[(size_t)MPAD * CH];   // attn out lo
__device__ __align__(256) __nv_bfloat16 g_pwhi[(size_t)CH * CH];
__device__ __align__(256) __nv_bfloat16 g_pwlo[(size_t)CH * CH];

// ---------------------------------------------------------------------------
// Baseline-PTX helpers (all legal on .target sm_103 — no 'a' features)
// ---------------------------------------------------------------------------
__device__ __forceinline__ uint32_t smem_u32(const void* p) {
    uint32_t a;
    asm("{ .reg .u64 t; cvta.to.shared.u64 t, %1; cvt.u32.u64 %0, t; }" : "=r"(a) : "l"(p));
    return a;
}
#define SMEM_SWIZZLE_128B(off) ((off) ^ (((off) >> 3) & 0x70))

#define CP_ASYNC_16(smem_addr, gptr) \
    asm volatile("cp.async.cg.shared.global [%0], [%1], 16;" \
        :: "r"(smem_addr), "l"(gptr) : "memory")
#define CP_ASYNC_COMMIT() asm volatile("cp.async.commit_group;" ::: "memory")
#define CP_ASYNC_WAIT(N)  asm volatile("cp.async.wait_group %0;" :: "n"(N) : "memory")

#define LDSM_X4(r0, r1, r2, r3, addr) \
    asm volatile("ldmatrix.sync.aligned.m8n8.x4.shared.b16 {%0,%1,%2,%3}, [%4];" \
        : "=r"(r0), "=r"(r1), "=r"(r2), "=r"(r3) : "r"(addr))

#define MMA_BF16(d, a0, a1, a2, a3, b0, b1) \
    asm volatile("mma.sync.aligned.m16n8k16.row.col.f32.bf16.bf16.f32 " \
        "{%0,%1,%2,%3}, {%4,%5,%6,%7}, {%8,%9}, {%0,%1,%2,%3};" \
        : "+f"((d)[0]), "+f"((d)[1]), "+f"((d)[2]), "+f"((d)[3]) \
        : "r"(a0), "r"(a1), "r"(a2), "r"(a3), "r"(b0), "r"(b1))

// ---------------------------------------------------------------------------
// Split fp32 -> (hi, lo) bf16, with tail zero-padding up to npad
// ---------------------------------------------------------------------------
__global__ void cvt_split(const float* __restrict__ in,
                          __nv_bfloat16* __restrict__ hi,
                          __nv_bfloat16* __restrict__ lo,
                          long long n, long long npad)
{
    long long i = (long long)blockIdx.x * blockDim.x + threadIdx.x;
    long long stride = (long long)gridDim.x * blockDim.x;
    for (; i < npad; i += stride) {
        float v = (i < n) ? in[i] : 0.0f;
        __nv_bfloat16 h = __float2bfloat16_rn(v);
        float r = v - __bfloat162float(h);
        hi[i] = h;
        lo[i] = __float2bfloat16_rn(r);
    }
}

// ---------------------------------------------------------------------------
// Warp-MMA split-bf16 GEMM: C[M,N] = A[M,K] @ B[N,K]^T + bias[N]
// CTA 128x128, 8 warps in 2(M)x4(N), warp tile 64x32.
// K chunks of 64; cp.async double-buffered smem; SW128-swizzled 128B rows.
// smem data at 1024: buf b at 1024 + b*65536:
//   Ahi 0 | Alo 16K | Bhi 32K | Blo 48K   (each 128 rows x 128 B)
// ---------------------------------------------------------------------------
#define GEMM_SMEM_BYTES (1024 + 2 * 65536)

__global__ __launch_bounds__(256, 1)
void mma_gemm(const __nv_bfloat16* __restrict__ Ahi, const __nv_bfloat16* __restrict__ Alo,
              const __nv_bfloat16* __restrict__ Bhi, const __nv_bfloat16* __restrict__ Blo,
              const float* __restrict__ bias, float* __restrict__ C,
              int Mstore, int N, int K)
{
    extern __shared__ char smem[];
    const uint32_t sbase = smem_u32(smem) + 1024;
    const int tid  = threadIdx.x;
    const int wid  = tid >> 5;
    const int lane = tid & 31;
    const int warp_m = wid >> 2;      // 0..1  (64 rows each)
    const int warp_n = wid & 3;       // 0..3  (32 cols each)

    const int bm = blockIdx.y * 128;
    const int bn = blockIdx.x * 128;
    const int nchunks = K / KCHUNK;   // 12

    // ---- global->smem async copy of one K-chunk into buffer `buf` ----
    const int r_lo = tid >> 3;        // 0..31
    const int u    = tid & 7;         // 16B unit within the 128B row
    auto issue_chunk = [&](int c, int buf) {
        const int k0 = c * KCHUNK;
        const uint32_t bb = sbase + buf * 65536;
#pragma unroll
        for (int it = 0; it < 4; it++) {
            const int r = it * 32 + r_lo;
            const uint32_t sw = SMEM_SWIZZLE_128B((uint32_t)(r * 128 + u * 16));
            const size_t ga = (size_t)(bm + r) * K + k0 + u * 8;
            const size_t gb = (size_t)(bn + r) * K + k0 + u * 8;
            CP_ASYNC_16(bb + 0     + sw, Ahi + ga);
            CP_ASYNC_16(bb + 16384 + sw, Alo + ga);
            CP_ASYNC_16(bb + 32768 + sw, Bhi + gb);
            CP_ASYNC_16(bb + 49152 + sw, Blo + gb);
        }
        CP_ASYNC_COMMIT();
    };

    // accumulators: 4 m-atoms x 4 n-atoms x 4 regs
    float acc[4][4][4];
#pragma unroll
    for (int mi = 0; mi < 4; mi++)
#pragma unroll
        for (int ni = 0; ni < 4; ni++)
#pragma unroll
            for (int q = 0; q < 4; q++) acc[mi][ni][q] = 0.0f;

    // ldmatrix lane addressing:
    // quad = lane>>3; row = base + (quad&1)*8 + (lane&7); colbytes += (quad>>1)*16
    const int quad = lane >> 3;
    const int l8   = lane & 7;
    const int lrow_a = warp_m * 64 + (quad & 1) * 8 + l8;   // + mi*16
    const int lrow_b = warp_n * 32 + (quad & 1) * 8 + l8;   // + ni2*16
    const int lcol   = (quad >> 1) * 16;                    // bytes; + ks*32

    issue_chunk(0, 0);

    for (int c = 0; c < nchunks; c++) {
        const int buf = c & 1;
        if (c + 1 < nchunks) {
            issue_chunk(c + 1, (c + 1) & 1);
            CP_ASYNC_WAIT(1);
        } else {
            CP_ASYNC_WAIT(0);
        }
        __syncthreads();

        const uint32_t bb = sbase + buf * 65536;
#pragma unroll
        for (int ks = 0; ks < 4; ks++) {
            const int kb = ks * 32 + lcol;   // byte offset along K

            uint32_t ahi[4][4], alo[4][4];
#pragma unroll
            for (int mi = 0; mi < 4; mi++) {
                const uint32_t off = (uint32_t)((lrow_a + mi * 16) * 128 + kb);
                const uint32_t sw = SMEM_SWIZZLE_128B(off);
                LDSM_X4(ahi[mi][0], ahi[mi][1], ahi[mi][2], ahi[mi][3], bb + 0 + sw);
                LDSM_X4(alo[mi][0], alo[mi][1], alo[mi][2], alo[mi][3], bb + 16384 + sw);
            }
            uint32_t bhi[4][2], blo[4][2];
#pragma unroll
            for (int ni2 = 0; ni2 < 2; ni2++) {
                const uint32_t off = (uint32_t)((lrow_b + ni2 * 16) * 128 + kb);
                const uint32_t sw = SMEM_SWIZZLE_128B(off);
                uint32_t r0, r1, r2, r3;
                LDSM_X4(r0, r1, r2, r3, bb + 32768 + sw);
                bhi[ni2 * 2 + 0][0] = r0; bhi[ni2 * 2 + 0][1] = r2;
                bhi[ni2 * 2 + 1][0] = r1; bhi[ni2 * 2 + 1][1] = r3;
                LDSM_X4(r0, r1, r2, r3, bb + 49152 + sw);
                blo[ni2 * 2 + 0][0] = r0; blo[ni2 * 2 + 0][1] = r2;
                blo[ni2 * 2 + 1][0] = r1; blo[ni2 * 2 + 1][1] = r3;
            }

#pragma unroll
            for (int mi = 0; mi < 4; mi++)
#pragma unroll
                for (int ni = 0; ni < 4; ni++) {
                    MMA_BF16(acc[mi][ni], ahi[mi][0], ahi[mi][1], ahi[mi][2], ahi[mi][3],
                             bhi[ni][0], bhi[ni][1]);
                    MMA_BF16(acc[mi][ni], ahi[mi][0], ahi[mi][1], ahi[mi][2], ahi[mi][3],
                             blo[ni][0], blo[ni][1]);
                    MMA_BF16(acc[mi][ni], alo[mi][0], alo[mi][1], alo[mi][2], alo[mi][3],
                             bhi[ni][0], bhi[ni][1]);
                }
        }
        __syncthreads();
    }

    // ---- epilogue: acc -> C (+bias). c0,c1 -> row g, cols 2t,2t+1; c2,c3 -> row g+8
    const int g  = lane >> 2;
    const int t2 = (lane & 3) * 2;
#pragma unroll
    for (int mi = 0; mi < 4; mi++) {
        const int row0 = bm + warp_m * 64 + mi * 16 + g;
#pragma unroll
        for (int ni = 0; ni < 4; ni++) {
            const int col = bn + warp_n * 32 + ni * 8 + t2;
            const float b0 = bias[col], b1 = bias[col + 1];
            if (row0 < Mstore) {
                float2 v = make_float2(acc[mi][ni][0] + b0, acc[mi][ni][1] + b1);
                *(float2*)(C + (size_t)row0 * N + col) = v;
            }
            if (row0 + 8 < Mstore) {
                float2 v = make_float2(acc[mi][ni][2] + b0, acc[mi][ni][3] + b1);
                *(float2*)(C + (size_t)(row0 + 8) * N + col) = v;
            }
        }
    }
}

// ---------------------------------------------------------------------------
// Fused attention: one CTA per (batch, head). Writes the attention output
// DIRECTLY as split (hi, lo) bf16 — same formula as cvt_split on the same
// fp32 value, so numerically identical to the separate pass it replaces.
// ---------------------------------------------------------------------------
#define KT_LD   200
#define SMEM_FLOATS (64 * KT_LD + NTOK * HDIM + 8 * HDIM + 8 * KT_LD)

__global__ __launch_bounds__(256, 1)
void attn_kernel(const float* __restrict__ h,
                 __nv_bfloat16* __restrict__ ohi,
                 __nv_bfloat16* __restrict__ olo)
{
    extern __shared__ float smemf[];
    float* Kt = smemf;                         // [64][200]
    float* Vs = Kt + 64 * KT_LD;               // [197][64]
    float* Qb = Vs + NTOK * HDIM;              // [8][64]
    float* Pb = Qb + 8 * HDIM;                 // [8][200]

    const int bh = blockIdx.x;
    const int b  = bh / NHEAD;
    const int hd = bh % NHEAD;

    const int tid  = threadIdx.x;
    const int w    = tid >> 5;
    const int lane = tid & 31;

    const float* hb = h + (size_t)b * NTOK * QKV_N;
    const int kcol = CH + hd * HDIM;
    const int vcol = 2 * CH + hd * HDIM;
    const int qcol = hd * HDIM;

    for (int idx = tid; idx < NTOK * HDIM; idx += 256) {
        int j = idx >> 6;
        int d = idx & 63;
        float kv = hb[(size_t)j * QKV_N + kcol + d];
        float vv = hb[(size_t)j * QKV_N + vcol + d];
        Kt[d * KT_LD + j] = kv;
        Vs[j * HDIM + d]  = vv;
    }
    __syncthreads();

    const float scale = 0.125f;

    for (int row = w; row < NTOK; row += 8) {
        for (int d = lane; d < HDIM; d += 32)
            Qb[w * HDIM + d] = hb[(size_t)row * QKV_N + qcol + d];
        __syncwarp();

        float s[7];
#pragma unroll
        for (int jj = 0; jj < 7; jj++) s[jj] = 0.0f;

#pragma unroll 4
        for (int d = 0; d < HDIM; d++) {
            float qd = Qb[w * HDIM + d];
            const float* krow = Kt + d * KT_LD;
#pragma unroll
            for (int jj = 0; jj < 7; jj++)
                s[jj] = fmaf(qd, krow[lane + jj * 32], s[jj]);
        }

        float mx = -INFINITY;
#pragma unroll
        for (int jj = 0; jj < 7; jj++) {
            int j = lane + jj * 32;
            if (j < NTOK) { s[jj] *= scale; mx = fmaxf(mx, s[jj]); }
            else s[jj] = -INFINITY;
        }
#pragma unroll
        for (int o = 16; o > 0; o >>= 1)
            mx = fmaxf(mx, __shfl_xor_sync(0xffffffffu, mx, o));

        float sum = 0.0f;
#pragma unroll
        for (int jj = 0; jj < 7; jj++) {
            s[jj] = expf(s[jj] - mx);
            sum += s[jj];
        }
#pragma unroll
        for (int o = 16; o > 0; o >>= 1)
            sum += __shfl_xor_sync(0xffffffffu, sum, o);
        float inv = 1.0f / sum;

#pragma unroll
        for (int jj = 0; jj < 7; jj++) {
            int j = lane + jj * 32;
            if (j < NTOK) Pb[w * KT_LD + j] = s[jj] * inv;
        }
        __syncwarp();

        const size_t obase = ((size_t)b * NTOK + row) * CH + hd * HDIM;
        const float* prow = Pb + w * KT_LD;
#pragma unroll
        for (int dd = 0; dd < 2; dd++) {
            int d = lane + dd * 32;
            float acc = 0.0f;
#pragma unroll 4
            for (int j = 0; j < NTOK; j++)
                acc = fmaf(prow[j], Vs[j * HDIM + d], acc);
            __nv_bfloat16 hv = __float2bfloat16_rn(acc);
            ohi[obase + d] = hv;
            olo[obase + d] = __float2bfloat16_rn(acc - __bfloat162float(hv));
        }
        __syncwarp();
    }
}

// ---------------------------------------------------------------------------
// Launch
// ---------------------------------------------------------------------------
extern "C" void kernel_launch(void* const* d_in, const int* in_sizes, int n_in,
                              void* d_out, int out_size)
{
    const float* x      = (const float*)d_in[0];
    const float* qkv_w  = (const float*)d_in[1];
    const float* qkv_b  = (const float*)d_in[2];
    const float* proj_w = (const float*)d_in[3];
    const float* proj_b = (const float*)d_in[4];
    float* out = (float*)d_out;

    float *h_buf;
    __nv_bfloat16 *xhi, *xlo, *whi, *wlo, *ahi, *alo, *pwhi, *pwlo;
    cudaGetSymbolAddress((void**)&h_buf, g_h);
    cudaGetSymbolAddress((void**)&xhi, g_xhi);
    cudaGetSymbolAddress((void**)&xlo, g_xlo);
    cudaGetSymbolAddress((void**)&whi, g_whi);
    cudaGetSymbolAddress((void**)&wlo, g_wlo);
    cudaGetSymbolAddress((void**)&ahi, g_ahi);
    cudaGetSymbolAddress((void**)&alo, g_alo);
    cudaGetSymbolAddress((void**)&pwhi, g_pwhi);
    cudaGetSymbolAddress((void**)&pwlo, g_pwlo);

    cudaFuncSetAttribute(mma_gemm, cudaFuncAttributeMaxDynamicSharedMemorySize, GEMM_SMEM_BYTES);

    // 0) split inputs into hi/lo bf16 (x padded to MPAD rows)
    cvt_split<<<2048, 256>>>(x, xhi, xlo, (long long)MROWS * CH, (long long)MPAD * CH);
    cvt_split<<<512, 256>>>(qkv_w, whi, wlo, (long long)QKV_N * CH, (long long)QKV_N * CH);
    cvt_split<<<256, 256>>>(proj_w, pwhi, pwlo, (long long)CH * CH, (long long)CH * CH);

    // 1) QKV GEMM: g_h[MPAD, 2304] = x @ Wqkv^T + b   (warp-MMA, split-bf16)
    {
        dim3 grid(QKV_N / 128, MPAD / 128);   // 18 x 99
        mma_gemm<<<grid, 256, GEMM_SMEM_BYTES>>>(xhi, xlo, whi, wlo, qkv_b, h_buf,
                                                 MPAD, QKV_N, KDIM);
    }

    // 2) fused attention -> writes split (hi, lo) bf16 directly.
    //    Padding rows MROWS..MPAD of ahi/alo stay uninitialized: GEMM rows are
    //    independent and the proj epilogue is guarded by Mstore=MROWS, so
    //    garbage there is computed-and-discarded, never stored.
    {
        size_t smem_bytes = (size_t)SMEM_FLOATS * sizeof(float);
        cudaFuncSetAttribute(attn_kernel, cudaFuncAttributeMaxDynamicSharedMemorySize,
                             (int)smem_bytes);
        attn_kernel<<<BATCH * NHEAD, 256, smem_bytes>>>(h_buf, ahi, alo);
    }

    // 3) proj GEMM: out[12608, 768] = att @ Wp^T + bp
    {
        dim3 grid(CH / 128, MPAD / 128);      // 6 x 99
        mma_gemm<<<grid, 256, GEMM_SMEM_BYTES>>>(ahi, alo, pwhi, pwlo, proj_b, out,
                                                 MROWS, CH, KDIM);
    }
}